// round 16
// baseline (speedup 1.0000x reference)
#include <cuda_runtime.h>

#define BB    8
#define DD    472
#define CC    472
#define FHH   56
#define FWW   100
#define NPIX  (FHH * FWW)      // 5600
#define NXX   160
#define NYY   160
#define NSEG  (BB * NXX * NYY) // 204800

#define SEGS       8
#define BINS_SEG   59                      // 8 * 59 = 472
#define ARG_BLOCKS ((BB * NPIX) / 32)      // 1400
#define ZERO_BLOCKS 8072                   // full waves with ARG
#define NCHUNK     (CC / 4)                // 118 float4 chunks
#define NGRP       (BB * NPIX / 8)         // 5600 groups of 8 pixels
#define SP         476                     // smem pitch (floats): conflict-free

// per-pixel BEV segment (or -1), rewritten fully every launch
__device__ int pix2seg_g[BB * NPIX];
// dedup linked list: head_g[seg] = pix+1 (0 = empty, self-cleaning), next chain
__device__ int head_g[NSEG];
__device__ int next_g[BB * NPIX];

__device__ __forceinline__ void inv3x3(const float a[9], float m[9]) {
    float A  =  (a[4] * a[8] - a[5] * a[7]);
    float Bc = -(a[3] * a[8] - a[5] * a[6]);
    float Cc =  (a[3] * a[7] - a[4] * a[6]);
    float Dv = -(a[1] * a[8] - a[2] * a[7]);
    float E  =  (a[0] * a[8] - a[2] * a[6]);
    float F  = -(a[0] * a[7] - a[1] * a[6]);
    float G  =  (a[1] * a[5] - a[2] * a[4]);
    float Hc = -(a[0] * a[5] - a[2] * a[3]);
    float I  =  (a[0] * a[4] - a[1] * a[3]);
    float det = a[0] * A + a[1] * Bc + a[2] * Cc;
    m[0] = A  / det;  m[1] = Dv / det;  m[2] = G  / det;
    m[3] = Bc / det;  m[4] = E  / det;  m[5] = Hc / det;
    m[6] = Cc / det;  m[7] = F  / det;  m[8] = I  / det;
}

// Fused: blocks [0, ARG_BLOCKS) -> argmax + geometry -> pix2seg + seg lists,
//        (PDL trigger after writes). Blocks [ARG_BLOCKS,...) -> zero-fill.
__global__ void __launch_bounds__(256)
fused_kernel(const float* __restrict__ depth,   // [B, D, FH, FW]
             const float* __restrict__ intr,    // [B, 3, 3]
             const float* __restrict__ rot,     // [B, 3, 3]
             float* __restrict__ out,           // [B, NX, NY, C]
             long long nout)
{
    if (blockIdx.x >= ARG_BLOCKS) {
        cudaTriggerProgrammaticLaunchCompletion();
        long long n4 = nout >> 2;
        float4* o4 = reinterpret_cast<float4*>(out);
        long long i = (long long)(blockIdx.x - ARG_BLOCKS) * 256 + threadIdx.x;
        long long stride = (long long)ZERO_BLOCKS * 256;
        float4 z = make_float4(0.f, 0.f, 0.f, 0.f);
        for (; i < n4; i += stride) __stcs(&o4[i], z);
        return;
    }

    // ---- argmax: 32 pixels per block, 8 depth-segments (one warp each) ----
    int tx = threadIdx.x & 31;
    int ty = threadIdx.x >> 5;
    int pix = blockIdx.x * 32 + tx;
    int b  = pix / NPIX;
    int hw = pix - b * NPIX;

    const float* dp = depth + (size_t)b * DD * NPIX + hw;
    int base = ty * BINS_SEG;
    float best = dp[(size_t)base * NPIX];
    int   bi   = base;
    #pragma unroll
    for (int k = 1; k < BINS_SEG; k++) {
        float v = dp[(size_t)(base + k) * NPIX];
        if (v > best) { best = v; bi = base + k; }
    }

    __shared__ float sval[SEGS][32];
    __shared__ int   sidx[SEGS][32];
    sval[ty][tx] = best;
    sidx[ty][tx] = bi;
    __syncthreads();

    if (ty == 0) {
        float bv = sval[0][tx];
        int  bix = sidx[0][tx];
        #pragma unroll
        for (int s = 1; s < SEGS; s++) {
            float v = sval[s][tx];
            if (v > bv) { bv = v; bix = sidx[s][tx]; }
        }
        float d = (float)bix * 0.125f + 1.0f;

        float a[9], invK[9], Cm[9];
        #pragma unroll
        for (int i = 0; i < 9; i++) a[i] = intr[b * 9 + i];
        inv3x3(a, invK);
        #pragma unroll
        for (int i = 0; i < 3; i++) {
            #pragma unroll
            for (int j = 0; j < 3; j++) {
                float acc = rot[b * 9 + i * 3 + 0] * invK[0 * 3 + j];
                acc = fmaf(rot[b * 9 + i * 3 + 1], invK[1 * 3 + j], acc);
                acc = fmaf(rot[b * 9 + i * 3 + 2], invK[2 * 3 + j], acc);
                Cm[i * 3 + j] = acc;
            }
        }

        int h = hw / FWW;
        int w = hw - h * FWW;
        const float DU = 1600.0f / 99.0f;
        const float DV = 896.0f / 55.0f;
        float u  = (float)w * DU;
        float v  = (float)h * DV;
        float ud = u * d;
        float vd = v * d;

        float x = fmaf(Cm[2], d, fmaf(Cm[1], vd, Cm[0] * ud));
        float y = fmaf(Cm[5], d, fmaf(Cm[4], vd, Cm[3] * ud));
        float z = fmaf(Cm[8], d, fmaf(Cm[7], vd, Cm[6] * ud));

        bool inb = (x > 1.0f) && (x < 41.0f) &&
                   (y > -20.0f) && (y < 20.0f) &&
                   (z > -10.0f) && (z < 10.0f);
        float fxv = floorf((x - 1.0f) * 4.0f);
        float fyv = floorf((y + 20.0f) * 4.0f);
        float fzv = floorf((z + 10.0f) / 20.0f);
        int xi = (int)fxv, yi = (int)fyv, zi = (int)fzv;
        bool ing = (xi >= 0) && (xi < NXX) && (yi >= 0) && (yi < NYY) &&
                   (zi >= 0) && (zi < 1);

        int seg = (inb && ing) ? ((b * NXX + xi) * NYY + yi) : -1;
        pix2seg_g[pix] = seg;
        if (seg >= 0) {
            int old = atomicExch(&head_g[seg], pix + 1);
            next_g[pix] = old;
        }
    }
    __syncthreads();
    __threadfence();
    cudaTriggerProgrammaticLaunchCompletion();
}

// Scatter: block = 8 consecutive pixels.
//  Phase A: sector-optimal coalesced loads into conflict-free smem.
//  Phase B (post-GridDepSync): only LIST-HEAD warps write — accumulate own
//  pixel from smem + rare duplicate pixels from global, then plain STG.128.cs
//  (no atomics at all). Head self-resets for the next graph replay.
__global__ void __launch_bounds__(256)
scatter_kernel(const float* __restrict__ feats,   // [B, C, FH, FW]
               float* __restrict__ out)           // [B*NX*NY, C]
{
    __shared__ float s[8 * SP];
    __shared__ int   segs[8];

    int tid  = threadIdx.x;
    int lane = tid & 31;
    int wid  = tid >> 5;
    int pix0 = blockIdx.x * 8;             // NPIX % 8 == 0: no batch straddle
    int b    = pix0 / NPIX;
    int hw0  = pix0 - b * NPIX;

    if (tid < 8) segs[tid] = __ldg(&pix2seg_g[pix0 + tid]);
    __syncthreads();

    bool any = false;
    #pragma unroll
    for (int p = 0; p < 8; p++) any |= (segs[p] >= 0);
    if (!any) return;

    // ---- Phase A: coalesced gather into smem (4 useful sectors per LDG) ----
    int p    = tid & 7;
    int crow = tid >> 3;                   // 0..31
    const float* fp = feats + (size_t)b * CC * NPIX + hw0 + p;
    #pragma unroll
    for (int i = 0; i < 15; i++) {
        int c = i * 32 + crow;
        if (c < CC)
            s[p * SP + c] = __ldg(&fp[(size_t)c * NPIX]);
    }
    __syncthreads();

    // zero-fill (and all list writes) complete before stores
    cudaGridDependencySynchronize();

    // ---- Phase B: head warps accumulate + plain streaming store ----
    int seg = segs[wid];                   // wid 0..7 = pixel within group
    if (seg < 0) return;
    int pix = pix0 + wid;
    int hd  = head_g[seg];                 // uniform across warp
    if (hd != pix + 1) return;             // duplicate: head handles it

    // own pixel's channels from smem
    float4 acc[4];
    const float4* sp = reinterpret_cast<const float4*>(&s[wid * SP]);
    bool has4 = (lane < NCHUNK - 96);      // lane < 22
    #pragma unroll
    for (int r = 0; r < 3; r++) acc[r] = sp[r * 32 + lane];
    if (has4) acc[3] = sp[96 + lane];

    // walk duplicate chain (rare, ~2% of segments)
    int nxt = next_g[pix];
    while (nxt != 0) {
        int p2  = nxt - 1;
        int b2  = p2 / NPIX;
        int hw2 = p2 - b2 * NPIX;
        const float* fp2 = feats + (size_t)b2 * CC * NPIX + hw2;
        #pragma unroll
        for (int r = 0; r < 3; r++) {
            int c = (r * 32 + lane) * 4;
            acc[r].x += __ldg(&fp2[(size_t)(c + 0) * NPIX]);
            acc[r].y += __ldg(&fp2[(size_t)(c + 1) * NPIX]);
            acc[r].z += __ldg(&fp2[(size_t)(c + 2) * NPIX]);
            acc[r].w += __ldg(&fp2[(size_t)(c + 3) * NPIX]);
        }
        if (has4) {
            int c = (96 + lane) * 4;
            acc[3].x += __ldg(&fp2[(size_t)(c + 0) * NPIX]);
            acc[3].y += __ldg(&fp2[(size_t)(c + 1) * NPIX]);
            acc[3].z += __ldg(&fp2[(size_t)(c + 2) * NPIX]);
            acc[3].w += __ldg(&fp2[(size_t)(c + 3) * NPIX]);
        }
        nxt = next_g[p2];
    }

    if (lane == 0) head_g[seg] = 0;        // self-clean for next replay

    float4* op = reinterpret_cast<float4*>(out + (size_t)seg * CC);
    #pragma unroll
    for (int r = 0; r < 3; r++) __stcs(&op[r * 32 + lane], acc[r]);
    if (has4) __stcs(&op[96 + lane], acc[3]);
}

extern "C" void kernel_launch(void* const* d_in, const int* in_sizes, int n_in,
                              void* d_out, int out_size) {
    const float* depth = (const float*)d_in[0];
    const float* feats = (const float*)d_in[1];
    const float* intr  = (const float*)d_in[2];
    const float* rot   = (const float*)d_in[3];
    float* out = (float*)d_out;

    fused_kernel<<<ARG_BLOCKS + ZERO_BLOCKS, 256>>>(depth, intr, rot, out,
                                                    (long long)out_size);

    cudaLaunchConfig_t cfg = {};
    cfg.gridDim  = dim3(NGRP, 1, 1);       // 5600 blocks
    cfg.blockDim = dim3(256, 1, 1);
    cfg.dynamicSmemBytes = 0;
    cfg.stream = 0;
    cudaLaunchAttribute attrs[1];
    attrs[0].id = cudaLaunchAttributeProgrammaticStreamSerialization;
    attrs[0].val.programmaticStreamSerializationAllowed = 1;
    cfg.attrs = attrs;
    cfg.numAttrs = 1;
    cudaLaunchKernelEx(&cfg, scatter_kernel, feats, out);
}

// round 17
// speedup vs baseline: 1.0269x; 1.0269x over previous
#include <cuda_runtime.h>

#define BB    8
#define DD    472
#define CC    472
#define FHH   56
#define FWW   100
#define NPIX  (FHH * FWW)      // 5600
#define NXX   160
#define NYY   160
#define NSEG  (BB * NXX * NYY) // 204800

#define SEGS       8
#define BINS_SEG   59                      // 8 * 59 = 472
#define ARG_BLOCKS ((BB * NPIX) / 32)      // 1400
#define ZERO_BLOCKS 8072                   // full waves with ARG
#define NCHUNK     (CC / 4)                // 118 float4 chunks
#define NGRP       (BB * NPIX / 8)         // 5600 groups of 8 pixels
#define SP         476                     // smem pitch (floats): conflict-free

// per-pixel BEV segment (or -1), rewritten fully every launch
__device__ int pix2seg_g[BB * NPIX];
// dedup list: head_g[seg] = pix+1 (0 empty); reset by matching scatter warp
__device__ int head_g[NSEG];
__device__ int next_g[BB * NPIX];

__device__ __forceinline__ void inv3x3(const float a[9], float m[9]) {
    float A  =  (a[4] * a[8] - a[5] * a[7]);
    float Bc = -(a[3] * a[8] - a[5] * a[6]);
    float Cc =  (a[3] * a[7] - a[4] * a[6]);
    float Dv = -(a[1] * a[8] - a[2] * a[7]);
    float E  =  (a[0] * a[8] - a[2] * a[6]);
    float F  = -(a[0] * a[7] - a[1] * a[6]);
    float G  =  (a[1] * a[5] - a[2] * a[4]);
    float Hc = -(a[0] * a[5] - a[2] * a[3]);
    float I  =  (a[0] * a[4] - a[1] * a[3]);
    float det = a[0] * A + a[1] * Bc + a[2] * Cc;
    m[0] = A  / det;  m[1] = Dv / det;  m[2] = G  / det;
    m[3] = Bc / det;  m[4] = E  / det;  m[5] = Hc / det;
    m[6] = Cc / det;  m[7] = F  / det;  m[8] = I  / det;
}

// Fused: blocks [0, ARG_BLOCKS) -> argmax + geometry -> pix2seg + dedup list,
//        (PDL trigger after writes). Blocks [ARG_BLOCKS,...) -> zero-fill.
__global__ void __launch_bounds__(256)
fused_kernel(const float* __restrict__ depth,   // [B, D, FH, FW]
             const float* __restrict__ intr,    // [B, 3, 3]
             const float* __restrict__ rot,     // [B, 3, 3]
             float* __restrict__ out,           // [B, NX, NY, C]
             long long nout)
{
    if (blockIdx.x >= ARG_BLOCKS) {
        cudaTriggerProgrammaticLaunchCompletion();
        long long n4 = nout >> 2;
        float4* o4 = reinterpret_cast<float4*>(out);
        long long i = (long long)(blockIdx.x - ARG_BLOCKS) * 256 + threadIdx.x;
        long long stride = (long long)ZERO_BLOCKS * 256;
        float4 z = make_float4(0.f, 0.f, 0.f, 0.f);
        for (; i < n4; i += stride) __stcs(&o4[i], z);
        return;
    }

    // ---- argmax: 32 pixels per block, 8 depth-segments (one warp each) ----
    int tx = threadIdx.x & 31;
    int ty = threadIdx.x >> 5;
    int pix = blockIdx.x * 32 + tx;
    int b  = pix / NPIX;
    int hw = pix - b * NPIX;

    const float* dp = depth + (size_t)b * DD * NPIX + hw;
    int base = ty * BINS_SEG;
    float best = dp[(size_t)base * NPIX];
    int   bi   = base;
    #pragma unroll
    for (int k = 1; k < BINS_SEG; k++) {
        float v = dp[(size_t)(base + k) * NPIX];
        if (v > best) { best = v; bi = base + k; }
    }

    __shared__ float sval[SEGS][32];
    __shared__ int   sidx[SEGS][32];
    sval[ty][tx] = best;
    sidx[ty][tx] = bi;
    __syncthreads();

    if (ty == 0) {
        float bv = sval[0][tx];
        int  bix = sidx[0][tx];
        #pragma unroll
        for (int s = 1; s < SEGS; s++) {
            float v = sval[s][tx];
            if (v > bv) { bv = v; bix = sidx[s][tx]; }
        }
        float d = (float)bix * 0.125f + 1.0f;

        float a[9], invK[9], Cm[9];
        #pragma unroll
        for (int i = 0; i < 9; i++) a[i] = intr[b * 9 + i];
        inv3x3(a, invK);
        #pragma unroll
        for (int i = 0; i < 3; i++) {
            #pragma unroll
            for (int j = 0; j < 3; j++) {
                float acc = rot[b * 9 + i * 3 + 0] * invK[0 * 3 + j];
                acc = fmaf(rot[b * 9 + i * 3 + 1], invK[1 * 3 + j], acc);
                acc = fmaf(rot[b * 9 + i * 3 + 2], invK[2 * 3 + j], acc);
                Cm[i * 3 + j] = acc;
            }
        }

        int h = hw / FWW;
        int w = hw - h * FWW;
        const float DU = 1600.0f / 99.0f;
        const float DV = 896.0f / 55.0f;
        float u  = (float)w * DU;
        float v  = (float)h * DV;
        float ud = u * d;
        float vd = v * d;

        float x = fmaf(Cm[2], d, fmaf(Cm[1], vd, Cm[0] * ud));
        float y = fmaf(Cm[5], d, fmaf(Cm[4], vd, Cm[3] * ud));
        float z = fmaf(Cm[8], d, fmaf(Cm[7], vd, Cm[6] * ud));

        bool inb = (x > 1.0f) && (x < 41.0f) &&
                   (y > -20.0f) && (y < 20.0f) &&
                   (z > -10.0f) && (z < 10.0f);
        float fxv = floorf((x - 1.0f) * 4.0f);
        float fyv = floorf((y + 20.0f) * 4.0f);
        float fzv = floorf((z + 10.0f) / 20.0f);
        int xi = (int)fxv, yi = (int)fyv, zi = (int)fzv;
        bool ing = (xi >= 0) && (xi < NXX) && (yi >= 0) && (yi < NYY) &&
                   (zi >= 0) && (zi < 1);

        int seg = (inb && ing) ? ((b * NXX + xi) * NYY + yi) : -1;
        pix2seg_g[pix] = seg;
        if (seg >= 0) {
            int old = atomicExch(&head_g[seg], pix + 1);
            next_g[pix] = old;
        }
    }
    __syncthreads();
    __threadfence();
    cudaTriggerProgrammaticLaunchCompletion();
}

// Scatter: block = 8 consecutive pixels.
//  PRE-sync : segs + heads loaded; sector-optimal feats gather into smem.
//  POST-sync: head warps only — add rare duplicate pixels (chain walk),
//             reset head, plain STG.128.cs. Zero atomics in the hot path.
__global__ void __launch_bounds__(256)
scatter_kernel(const float* __restrict__ feats,   // [B, C, FH, FW]
               float* __restrict__ out)           // [B*NX*NY, C]
{
    __shared__ float s[8 * SP];
    __shared__ int   segs[8];
    __shared__ int   hds[8];

    int tid  = threadIdx.x;
    int lane = tid & 31;
    int wid  = tid >> 5;
    int pix0 = blockIdx.x * 8;             // NPIX % 8 == 0: no batch straddle
    int b    = pix0 / NPIX;
    int hw0  = pix0 - b * NPIX;

    if (tid < 8) {
        int sg = __ldg(&pix2seg_g[pix0 + tid]);
        segs[tid] = sg;
        hds[tid]  = (sg >= 0) ? *((volatile int*)&head_g[sg]) : 0;
    }
    __syncthreads();

    bool any = false;
    #pragma unroll
    for (int p = 0; p < 8; p++) any |= (segs[p] >= 0);
    if (!any) return;

    // ---- Phase A: coalesced gather into smem (4 useful sectors per LDG) ----
    int p    = tid & 7;
    int crow = tid >> 3;                   // 0..31
    const float* fp = feats + (size_t)b * CC * NPIX + hw0 + p;
    #pragma unroll
    for (int i = 0; i < 15; i++) {
        int c = i * 32 + crow;
        if (c < CC)
            s[p * SP + c] = __ldg(&fp[(size_t)c * NPIX]);
    }
    __syncthreads();

    // zero-fill complete before our stores
    cudaGridDependencySynchronize();

    // ---- Phase B: head warps accumulate + streaming store ----
    int seg = segs[wid];                   // wid 0..7 = pixel within group
    if (seg < 0) return;
    int pix = pix0 + wid;
    if (hds[wid] != pix + 1) return;       // duplicate: its head handles it

    float4 acc[4];
    const float4* sp = reinterpret_cast<const float4*>(&s[wid * SP]);
    bool has4 = (lane < NCHUNK - 96);      // lane < 22
    #pragma unroll
    for (int r = 0; r < 3; r++) acc[r] = sp[r * 32 + lane];
    if (has4) acc[3] = sp[96 + lane];

    // duplicate chain (rare, ~2% of valid segments)
    int nxt = next_g[pix];
    while (nxt != 0) {
        int p2  = nxt - 1;
        int b2  = p2 / NPIX;
        int hw2 = p2 - b2 * NPIX;
        const float* fp2 = feats + (size_t)b2 * CC * NPIX + hw2;
        #pragma unroll
        for (int r = 0; r < 3; r++) {
            int c = (r * 32 + lane) * 4;
            acc[r].x += __ldg(&fp2[(size_t)(c + 0) * NPIX]);
            acc[r].y += __ldg(&fp2[(size_t)(c + 1) * NPIX]);
            acc[r].z += __ldg(&fp2[(size_t)(c + 2) * NPIX]);
            acc[r].w += __ldg(&fp2[(size_t)(c + 3) * NPIX]);
        }
        if (has4) {
            int c = (96 + lane) * 4;
            acc[3].x += __ldg(&fp2[(size_t)(c + 0) * NPIX]);
            acc[3].y += __ldg(&fp2[(size_t)(c + 1) * NPIX]);
            acc[3].z += __ldg(&fp2[(size_t)(c + 2) * NPIX]);
            acc[3].w += __ldg(&fp2[(size_t)(c + 3) * NPIX]);
        }
        nxt = next_g[p2];
    }

    if (lane == 0) head_g[seg] = 0;        // self-clean for next replay

    float4* op = reinterpret_cast<float4*>(out + (size_t)seg * CC);
    #pragma unroll
    for (int r = 0; r < 3; r++) __stcs(&op[r * 32 + lane], acc[r]);
    if (has4) __stcs(&op[96 + lane], acc[3]);
}

extern "C" void kernel_launch(void* const* d_in, const int* in_sizes, int n_in,
                              void* d_out, int out_size) {
    const float* depth = (const float*)d_in[0];
    const float* feats = (const float*)d_in[1];
    const float* intr  = (const float*)d_in[2];
    const float* rot   = (const float*)d_in[3];
    float* out = (float*)d_out;

    fused_kernel<<<ARG_BLOCKS + ZERO_BLOCKS, 256>>>(depth, intr, rot, out,
                                                    (long long)out_size);

    cudaLaunchConfig_t cfg = {};
    cfg.gridDim  = dim3(NGRP, 1, 1);       // 5600 blocks
    cfg.blockDim = dim3(256, 1, 1);
    cfg.dynamicSmemBytes = 0;
    cfg.stream = 0;
    cudaLaunchAttribute attrs[1];
    attrs[0].id = cudaLaunchAttributeProgrammaticStreamSerialization;
    attrs[0].val.programmaticStreamSerializationAllowed = 1;
    cfg.attrs = attrs;
    cfg.numAttrs = 1;
    cudaLaunchKernelEx(&cfg, scatter_kernel, feats, out);
}